// round 3
// baseline (speedup 1.0000x reference)
#include <cuda_runtime.h>

// Additive flow: 65 sequential steps of a 63->256->256->1 MLP per batch row,
// rows independent. Persistent row-tile per CTA, z tile lives in SMEM for all
// 65 steps. fp32 with packed f32x2 FMA (FFMA2, PTX-only path on sm_10x).

#define RTILE 64       // rows per CTA
#define ZS    68       // zs row stride in floats (pad: 16B-aligned, 4-way bank)
#define HS    68       // h1s row stride in floats
#define NCOLS 64       // N
#define HID   256

typedef unsigned long long ull;

__device__ __forceinline__ ull pack2(float x, float y) {
    ull r; asm("mov.b64 %0, {%1, %2};" : "=l"(r) : "f"(x), "f"(y)); return r;
}
__device__ __forceinline__ void unpack2(ull v, float &x, float &y) {
    asm("mov.b64 {%0, %1}, %2;" : "=f"(x), "=f"(y) : "l"(v));
}
__device__ __forceinline__ void ffma2(ull &d, ull a, ull b) {
    // d = a * b + d  (packed 2x fp32)
    asm("fma.rn.f32x2 %0, %1, %2, %0;" : "+l"(d) : "l"(a), "l"(b));
}

__global__ void __launch_bounds__(256, 2)
additive_flow_kernel(const float* __restrict__ x,
                     const float* __restrict__ s,
                     const float* __restrict__ W1,
                     const float* __restrict__ b1,
                     const float* __restrict__ W2,
                     const float* __restrict__ b2,
                     const float* __restrict__ W3,
                     const float* __restrict__ b3,
                     const int*   __restrict__ idx,
                     float* __restrict__ out,
                     int nsteps)
{
    extern __shared__ float smem[];
    float* zs   = smem;                       // [64][ZS]
    float* h1s  = zs + NCOLS * ZS;            // [256][HS]
    float* part = h1s + HID * HS;             // [64][8]

    const int tid  = threadIdx.x;
    const int lane = tid & 31;
    const int warp = tid >> 5;
    const long long row0 = (long long)blockIdx.x * RTILE;

    // Load z tile transposed: zs[col][row] = x[row0+row][col]
    for (int e = tid; e < RTILE * NCOLS; e += 256) {
        int col = e & (NCOLS - 1);
        int row = e >> 6;
        zs[col * ZS + row] = x[(row0 + row) * NCOLS + col];
    }
    __syncthreads();

    const int j = tid;  // hidden column owned by this thread

    for (int step = 0; step < nsteps; ++step) {
        const int   i   = idx[step];
        const float* W1p = W1 + (size_t)step * 63 * HID;
        const float* W2p = W2 + (size_t)step * HID * HID;
        const float b1v = b1[step * HID + j];
        const float b2v = b2[step * HID + j];
        const float w3v = W3[step * HID + j];

        ull acc[32];

        // ---------------- GEMM1: h1 = relu(v @ W1 + b1), v has 63 features
        {
            ull binit = pack2(b1v, b1v);
            #pragma unroll
            for (int p = 0; p < 32; ++p) acc[p] = binit;

            float wc[3];
            #pragma unroll
            for (int u = 0; u < 3; ++u) wc[u] = W1p[u * HID + j];

            #pragma unroll 1
            for (int kk = 0; kk < 63; kk += 3) {
                float wn[3];
                int kb = kk + 3; if (kb > 60) kb = 60;  // clamped prefetch
                #pragma unroll
                for (int u = 0; u < 3; ++u) wn[u] = W1p[(kb + u) * HID + j];

                #pragma unroll
                for (int u = 0; u < 3; ++u) {
                    const int k = kk + u;
                    // column substitution: feature k==i comes from z[:,63]
                    const float* zrow = zs + ((k == i) ? 63 : k) * ZS;
                    ull ww = pack2(wc[u], wc[u]);
                    #pragma unroll
                    for (int q = 0; q < 16; ++q) {
                        ulonglong2 v = *(const ulonglong2*)(zrow + 4 * q);
                        ffma2(acc[2 * q],     v.x, ww);
                        ffma2(acc[2 * q + 1], v.y, ww);
                    }
                }
                #pragma unroll
                for (int u = 0; u < 3; ++u) wc[u] = wn[u];
            }
        }

        // relu + store h1 transposed: h1s[feature=j][row]
        #pragma unroll
        for (int p = 0; p < 32; ++p) {
            float a, b; unpack2(acc[p], a, b);
            a = fmaxf(a, 0.f); b = fmaxf(b, 0.f);
            *(float2*)(h1s + j * HS + 2 * p) = make_float2(a, b);
        }
        __syncthreads();

        // ---------------- GEMM2: h2 = relu(h1 @ W2 + b2)
        {
            ull binit = pack2(b2v, b2v);
            #pragma unroll
            for (int p = 0; p < 32; ++p) acc[p] = binit;

            float wc[4];
            #pragma unroll
            for (int u = 0; u < 4; ++u) wc[u] = W2p[u * HID + j];

            #pragma unroll 1
            for (int kk = 0; kk < 256; kk += 4) {
                float wn[4];
                int kb = kk + 4; if (kb > 252) kb = 252;  // clamped prefetch
                #pragma unroll
                for (int u = 0; u < 4; ++u) wn[u] = W2p[(kb + u) * HID + j];

                #pragma unroll
                for (int u = 0; u < 4; ++u) {
                    const float* hrow = h1s + (kk + u) * HS;
                    ull ww = pack2(wc[u], wc[u]);
                    #pragma unroll
                    for (int q = 0; q < 16; ++q) {
                        ulonglong2 v = *(const ulonglong2*)(hrow + 4 * q);
                        ffma2(acc[2 * q],     v.x, ww);
                        ffma2(acc[2 * q + 1], v.y, ww);
                    }
                }
                #pragma unroll
                for (int u = 0; u < 4; ++u) wc[u] = wn[u];
            }
        }

        // ---------------- GEMM3: t[r] = sum_j relu(h2[r][j]) * w3[j] (+ b3)
        #pragma unroll
        for (int p = 0; p < 32; ++p) {
            float a, b; unpack2(acc[p], a, b);
            a = fmaxf(a, 0.f) * w3v;
            b = fmaxf(b, 0.f) * w3v;
            #pragma unroll
            for (int o = 16; o > 0; o >>= 1) {
                a += __shfl_xor_sync(0xffffffffu, a, o);
                b += __shfl_xor_sync(0xffffffffu, b, o);
            }
            if (lane == 0) {
                part[(2 * p)     * 8 + warp] = a;
                part[(2 * p + 1) * 8 + warp] = b;
            }
        }
        __syncthreads();

        if (tid < RTILE) {
            float t = b3[step];
            #pragma unroll
            for (int w = 0; w < 8; ++w) t += part[tid * 8 + w];
            const int tgt = (i < 63) ? i : 63;   // column receiving the update
            zs[tgt * ZS + tid] += t;
        }
        __syncthreads();
    }

    // Epilogue: out = exp(s) * z
    for (int e = tid; e < RTILE * NCOLS; e += 256) {
        int col = e & (NCOLS - 1);
        int row = e >> 6;
        out[(row0 + row) * NCOLS + col] = expf(s[col]) * zs[col * ZS + row];
    }
}

extern "C" void kernel_launch(void* const* d_in, const int* in_sizes, int n_in,
                              void* d_out, int out_size)
{
    const float* x   = (const float*)d_in[0];
    const float* s   = (const float*)d_in[1];
    const float* W1  = (const float*)d_in[2];
    const float* b1  = (const float*)d_in[3];
    const float* W2  = (const float*)d_in[4];
    const float* b2  = (const float*)d_in[5];
    const float* W3  = (const float*)d_in[6];
    const float* b3  = (const float*)d_in[7];
    const int*   idx = (const int*)d_in[8];
    float* out = (float*)d_out;

    const int B      = in_sizes[0] / NCOLS;   // 131072
    const int nsteps = in_sizes[8];           // 65

    const int smem_bytes = (NCOLS * ZS + HID * HS + RTILE * 8) * (int)sizeof(float); // 89088

    cudaFuncSetAttribute(additive_flow_kernel,
                         cudaFuncAttributeMaxDynamicSharedMemorySize, smem_bytes);

    dim3 grid(B / RTILE);   // 2048 CTAs
    dim3 block(256);
    additive_flow_kernel<<<grid, block, smem_bytes>>>(
        x, s, W1, b1, W2, b2, W3, b3, idx, out, nsteps);
}

// round 4
// speedup vs baseline: 1.4500x; 1.4500x over previous
#include <cuda_runtime.h>

// Additive flow: 65 sequential steps of a 63->256->256->1 MLP per batch row,
// rows independent. Persistent 64-row tile per CTA kept in SMEM across all
// steps. fp32 with packed f32x2 FMA (FFMA2). Register blocking: each thread
// computes a 16-row x 4-col tile of each hidden layer, so each broadcast
// LDS.128 feeds 8 FFMA2 (was 2 in the previous version -> L1 was binding).

#define RTILE 64       // rows per CTA
#define ZS    68       // zs row stride in floats (16B aligned, conflict-free f4)
#define HS    68       // h1s row stride in floats
#define NCOLS 64       // N
#define HID   256

typedef unsigned long long ull;

__device__ __forceinline__ ull pack2(float x, float y) {
    ull r; asm("mov.b64 %0, {%1, %2};" : "=l"(r) : "f"(x), "f"(y)); return r;
}
__device__ __forceinline__ void unpack2(ull v, float &x, float &y) {
    asm("mov.b64 {%0, %1}, %2;" : "=f"(x), "=f"(y) : "l"(v));
}
__device__ __forceinline__ void ffma2(ull &d, ull a, ull b) {
    // d = a * b + d  (packed 2x fp32)
    asm("fma.rn.f32x2 %0, %1, %2, %0;" : "+l"(d) : "l"(a), "l"(b));
}

__global__ void __launch_bounds__(256, 2)
additive_flow_kernel(const float* __restrict__ x,
                     const float* __restrict__ s,
                     const float* __restrict__ W1,
                     const float* __restrict__ b1,
                     const float* __restrict__ W2,
                     const float* __restrict__ b2,
                     const float* __restrict__ W3,
                     const float* __restrict__ b3,
                     const int*   __restrict__ idx,
                     float* __restrict__ out,
                     int nsteps)
{
    extern __shared__ float smem[];
    float* zs   = smem;                       // [64][ZS]   z tile, col-major
    float* h1s  = zs + NCOLS * ZS;            // [256][HS]  h1, feature-major
    float* part = h1s + HID * HS;             // [64][2]    GEMM3 partials

    const int tid  = threadIdx.x;
    const int lane = tid & 31;
    const int warp = tid >> 5;
    const int c0   = tid & 63;                // base hidden column
    const int g    = tid >> 6;                // row group (0..3)
    const int r0   = g * 16;                  // first row of this thread
    const long long row0 = (long long)blockIdx.x * RTILE;

    // Load z tile transposed: zs[col][row] = x[row0+row][col]
    for (int e = tid; e < RTILE * NCOLS; e += 256) {
        int col = e & (NCOLS - 1);
        int row = e >> 6;
        zs[col * ZS + row] = x[(row0 + row) * NCOLS + col];
    }
    __syncthreads();

    for (int step = 0; step < nsteps; ++step) {
        const int    i   = idx[step];
        const float* W1p = W1 + (size_t)step * 63 * HID;
        const float* W2p = W2 + (size_t)step * HID * HID;

        float b1v[4], b2v[4], w3v[4];
        #pragma unroll
        for (int c = 0; c < 4; ++c) {
            b1v[c] = b1[step * HID + c0 + 64 * c];
            b2v[c] = b2[step * HID + c0 + 64 * c];
            w3v[c] = W3[step * HID + c0 + 64 * c];
        }

        ull acc[4][8];   // [col][packed row pair]

        // ---------------- GEMM1: h1 = relu(v @ W1 + b1), 63 features
        {
            #pragma unroll
            for (int c = 0; c < 4; ++c) {
                ull bi = pack2(b1v[c], b1v[c]);
                #pragma unroll
                for (int p = 0; p < 8; ++p) acc[c][p] = bi;
            }

            float w[4], wn[4];
            #pragma unroll
            for (int c = 0; c < 4; ++c) w[c] = W1p[c0 + 64 * c];

            #pragma unroll 1
            for (int k = 0; k < 63; ++k) {
                const int kn = (k + 1 < 63) ? k + 1 : 62;
                #pragma unroll
                for (int c = 0; c < 4; ++c) wn[c] = W1p[kn * HID + c0 + 64 * c];

                // column substitution: feature k==i comes from z[:,63]
                const float* zr = zs + ((k == i) ? 63 : k) * ZS + r0;
                ulonglong2 v0 = *(const ulonglong2*)(zr);
                ulonglong2 v1 = *(const ulonglong2*)(zr + 4);
                ulonglong2 v2 = *(const ulonglong2*)(zr + 8);
                ulonglong2 v3 = *(const ulonglong2*)(zr + 12);
                ull vv[8] = {v0.x, v0.y, v1.x, v1.y, v2.x, v2.y, v3.x, v3.y};

                #pragma unroll
                for (int c = 0; c < 4; ++c) {
                    ull ww = pack2(w[c], w[c]);
                    #pragma unroll
                    for (int p = 0; p < 8; ++p) ffma2(acc[c][p], vv[p], ww);
                }
                #pragma unroll
                for (int c = 0; c < 4; ++c) w[c] = wn[c];
            }
        }

        // relu + store h1 feature-major: h1s[col][row], float4 stores
        #pragma unroll
        for (int c = 0; c < 4; ++c) {
            float* hp = h1s + (c0 + 64 * c) * HS + r0;
            #pragma unroll
            for (int p = 0; p < 4; ++p) {
                float a0, a1, a2, a3;
                unpack2(acc[c][2 * p],     a0, a1);
                unpack2(acc[c][2 * p + 1], a2, a3);
                float4 f4 = make_float4(fmaxf(a0, 0.f), fmaxf(a1, 0.f),
                                        fmaxf(a2, 0.f), fmaxf(a3, 0.f));
                *(float4*)(hp + 4 * p) = f4;
            }
        }
        __syncthreads();

        // ---------------- GEMM2: h2 = relu(h1 @ W2 + b2), K = 256
        {
            #pragma unroll
            for (int c = 0; c < 4; ++c) {
                ull bi = pack2(b2v[c], b2v[c]);
                #pragma unroll
                for (int p = 0; p < 8; ++p) acc[c][p] = bi;
            }

            float w[4], wn[4];
            #pragma unroll
            for (int c = 0; c < 4; ++c) w[c] = W2p[c0 + 64 * c];

            #pragma unroll 2
            for (int k = 0; k < HID; ++k) {
                const int kn = (k + 1 < HID) ? k + 1 : HID - 1;
                #pragma unroll
                for (int c = 0; c < 4; ++c) wn[c] = W2p[kn * HID + c0 + 64 * c];

                const float* hr = h1s + k * HS + r0;
                ulonglong2 v0 = *(const ulonglong2*)(hr);
                ulonglong2 v1 = *(const ulonglong2*)(hr + 4);
                ulonglong2 v2 = *(const ulonglong2*)(hr + 8);
                ulonglong2 v3 = *(const ulonglong2*)(hr + 12);
                ull vv[8] = {v0.x, v0.y, v1.x, v1.y, v2.x, v2.y, v3.x, v3.y};

                #pragma unroll
                for (int c = 0; c < 4; ++c) {
                    ull ww = pack2(w[c], w[c]);
                    #pragma unroll
                    for (int p = 0; p < 8; ++p) ffma2(acc[c][p], vv[p], ww);
                }
                #pragma unroll
                for (int c = 0; c < 4; ++c) w[c] = wn[c];
            }
        }

        // ---------------- GEMM3: t[r] = b3 + sum_j relu(h2[r][j]) * w3[j]
        // Each thread: relu * w3, sum its 4 cols -> 16 row partials, then
        // butterfly-reduce over the warp (32 distinct c0 values).
        #pragma unroll
        for (int p = 0; p < 8; ++p) {
            float sa = 0.f, sb = 0.f;
            #pragma unroll
            for (int c = 0; c < 4; ++c) {
                float a, b; unpack2(acc[c][p], a, b);
                sa = fmaf(fmaxf(a, 0.f), w3v[c], sa);
                sb = fmaf(fmaxf(b, 0.f), w3v[c], sb);
            }
            #pragma unroll
            for (int o = 16; o > 0; o >>= 1) {
                sa += __shfl_xor_sync(0xffffffffu, sa, o);
                sb += __shfl_xor_sync(0xffffffffu, sb, o);
            }
            if (lane == 0) {
                // warps 2g and 2g+1 cover c0-halves of row group g
                part[(r0 + 2 * p)     * 2 + (warp & 1)] = sa;
                part[(r0 + 2 * p + 1) * 2 + (warp & 1)] = sb;
            }
        }
        __syncthreads();

        if (tid < RTILE) {
            float t = b3[step] + part[tid * 2] + part[tid * 2 + 1];
            const int tgt = (i < 63) ? i : 63;   // column receiving the update
            zs[tgt * ZS + tid] += t;
        }
        __syncthreads();
    }

    // Epilogue: out = exp(s) * z
    for (int e = tid; e < RTILE * NCOLS; e += 256) {
        int col = e & (NCOLS - 1);
        int row = e >> 6;
        out[(row0 + row) * NCOLS + col] = expf(s[col]) * zs[col * ZS + row];
    }
}

extern "C" void kernel_launch(void* const* d_in, const int* in_sizes, int n_in,
                              void* d_out, int out_size)
{
    const float* x   = (const float*)d_in[0];
    const float* s   = (const float*)d_in[1];
    const float* W1  = (const float*)d_in[2];
    const float* b1  = (const float*)d_in[3];
    const float* W2  = (const float*)d_in[4];
    const float* b2  = (const float*)d_in[5];
    const float* W3  = (const float*)d_in[6];
    const float* b3  = (const float*)d_in[7];
    const int*   idx = (const int*)d_in[8];
    float* out = (float*)d_out;

    const int B      = in_sizes[0] / NCOLS;   // 131072
    const int nsteps = in_sizes[8];           // 65

    const int smem_bytes = (NCOLS * ZS + HID * HS + RTILE * 2) * (int)sizeof(float);

    cudaFuncSetAttribute(additive_flow_kernel,
                         cudaFuncAttributeMaxDynamicSharedMemorySize, smem_bytes);

    dim3 grid(B / RTILE);   // 2048 CTAs
    dim3 block(256);
    additive_flow_kernel<<<grid, block, smem_bytes>>>(
        x, s, W1, b1, W2, b2, W3, b3, idx, out, nsteps);
}

// round 5
// speedup vs baseline: 1.4501x; 1.0000x over previous
#include <cuda_runtime.h>

// Additive flow: 65 sequential steps of a 63->256->256->1 MLP per batch row,
// rows independent. Persistent 64-row tile per CTA kept in SMEM across all
// steps. fp32 with packed f32x2 FMA (FFMA2). Register blocking: each thread
// computes a 16-row x 4-col tile of each hidden layer, so each broadcast
// LDS.128 feeds 8 FFMA2 (was 2 in the previous version -> L1 was binding).

#define RTILE 64       // rows per CTA
#define ZS    68       // zs row stride in floats (16B aligned, conflict-free f4)
#define HS    68       // h1s row stride in floats
#define NCOLS 64       // N
#define HID   256

typedef unsigned long long ull;

__device__ __forceinline__ ull pack2(float x, float y) {
    ull r; asm("mov.b64 %0, {%1, %2};" : "=l"(r) : "f"(x), "f"(y)); return r;
}
__device__ __forceinline__ void unpack2(ull v, float &x, float &y) {
    asm("mov.b64 {%0, %1}, %2;" : "=f"(x), "=f"(y) : "l"(v));
}
__device__ __forceinline__ void ffma2(ull &d, ull a, ull b) {
    // d = a * b + d  (packed 2x fp32)
    asm("fma.rn.f32x2 %0, %1, %2, %0;" : "+l"(d) : "l"(a), "l"(b));
}

__global__ void __launch_bounds__(256, 2)
additive_flow_kernel(const float* __restrict__ x,
                     const float* __restrict__ s,
                     const float* __restrict__ W1,
                     const float* __restrict__ b1,
                     const float* __restrict__ W2,
                     const float* __restrict__ b2,
                     const float* __restrict__ W3,
                     const float* __restrict__ b3,
                     const int*   __restrict__ idx,
                     float* __restrict__ out,
                     int nsteps)
{
    extern __shared__ float smem[];
    float* zs   = smem;                       // [64][ZS]   z tile, col-major
    float* h1s  = zs + NCOLS * ZS;            // [256][HS]  h1, feature-major
    float* part = h1s + HID * HS;             // [64][2]    GEMM3 partials

    const int tid  = threadIdx.x;
    const int lane = tid & 31;
    const int warp = tid >> 5;
    const int c0   = tid & 63;                // base hidden column
    const int g    = tid >> 6;                // row group (0..3)
    const int r0   = g * 16;                  // first row of this thread
    const long long row0 = (long long)blockIdx.x * RTILE;

    // Load z tile transposed: zs[col][row] = x[row0+row][col]
    for (int e = tid; e < RTILE * NCOLS; e += 256) {
        int col = e & (NCOLS - 1);
        int row = e >> 6;
        zs[col * ZS + row] = x[(row0 + row) * NCOLS + col];
    }
    __syncthreads();

    for (int step = 0; step < nsteps; ++step) {
        const int    i   = idx[step];
        const float* W1p = W1 + (size_t)step * 63 * HID;
        const float* W2p = W2 + (size_t)step * HID * HID;

        float b1v[4], b2v[4], w3v[4];
        #pragma unroll
        for (int c = 0; c < 4; ++c) {
            b1v[c] = b1[step * HID + c0 + 64 * c];
            b2v[c] = b2[step * HID + c0 + 64 * c];
            w3v[c] = W3[step * HID + c0 + 64 * c];
        }

        ull acc[4][8];   // [col][packed row pair]

        // ---------------- GEMM1: h1 = relu(v @ W1 + b1), 63 features
        {
            #pragma unroll
            for (int c = 0; c < 4; ++c) {
                ull bi = pack2(b1v[c], b1v[c]);
                #pragma unroll
                for (int p = 0; p < 8; ++p) acc[c][p] = bi;
            }

            float w[4], wn[4];
            #pragma unroll
            for (int c = 0; c < 4; ++c) w[c] = W1p[c0 + 64 * c];

            #pragma unroll 1
            for (int k = 0; k < 63; ++k) {
                const int kn = (k + 1 < 63) ? k + 1 : 62;
                #pragma unroll
                for (int c = 0; c < 4; ++c) wn[c] = W1p[kn * HID + c0 + 64 * c];

                // column substitution: feature k==i comes from z[:,63]
                const float* zr = zs + ((k == i) ? 63 : k) * ZS + r0;
                ulonglong2 v0 = *(const ulonglong2*)(zr);
                ulonglong2 v1 = *(const ulonglong2*)(zr + 4);
                ulonglong2 v2 = *(const ulonglong2*)(zr + 8);
                ulonglong2 v3 = *(const ulonglong2*)(zr + 12);
                ull vv[8] = {v0.x, v0.y, v1.x, v1.y, v2.x, v2.y, v3.x, v3.y};

                #pragma unroll
                for (int c = 0; c < 4; ++c) {
                    ull ww = pack2(w[c], w[c]);
                    #pragma unroll
                    for (int p = 0; p < 8; ++p) ffma2(acc[c][p], vv[p], ww);
                }
                #pragma unroll
                for (int c = 0; c < 4; ++c) w[c] = wn[c];
            }
        }

        // relu + store h1 feature-major: h1s[col][row], float4 stores
        #pragma unroll
        for (int c = 0; c < 4; ++c) {
            float* hp = h1s + (c0 + 64 * c) * HS + r0;
            #pragma unroll
            for (int p = 0; p < 4; ++p) {
                float a0, a1, a2, a3;
                unpack2(acc[c][2 * p],     a0, a1);
                unpack2(acc[c][2 * p + 1], a2, a3);
                float4 f4 = make_float4(fmaxf(a0, 0.f), fmaxf(a1, 0.f),
                                        fmaxf(a2, 0.f), fmaxf(a3, 0.f));
                *(float4*)(hp + 4 * p) = f4;
            }
        }
        __syncthreads();

        // ---------------- GEMM2: h2 = relu(h1 @ W2 + b2), K = 256
        {
            #pragma unroll
            for (int c = 0; c < 4; ++c) {
                ull bi = pack2(b2v[c], b2v[c]);
                #pragma unroll
                for (int p = 0; p < 8; ++p) acc[c][p] = bi;
            }

            float w[4], wn[4];
            #pragma unroll
            for (int c = 0; c < 4; ++c) w[c] = W2p[c0 + 64 * c];

            #pragma unroll 2
            for (int k = 0; k < HID; ++k) {
                const int kn = (k + 1 < HID) ? k + 1 : HID - 1;
                #pragma unroll
                for (int c = 0; c < 4; ++c) wn[c] = W2p[kn * HID + c0 + 64 * c];

                const float* hr = h1s + k * HS + r0;
                ulonglong2 v0 = *(const ulonglong2*)(hr);
                ulonglong2 v1 = *(const ulonglong2*)(hr + 4);
                ulonglong2 v2 = *(const ulonglong2*)(hr + 8);
                ulonglong2 v3 = *(const ulonglong2*)(hr + 12);
                ull vv[8] = {v0.x, v0.y, v1.x, v1.y, v2.x, v2.y, v3.x, v3.y};

                #pragma unroll
                for (int c = 0; c < 4; ++c) {
                    ull ww = pack2(w[c], w[c]);
                    #pragma unroll
                    for (int p = 0; p < 8; ++p) ffma2(acc[c][p], vv[p], ww);
                }
                #pragma unroll
                for (int c = 0; c < 4; ++c) w[c] = wn[c];
            }
        }

        // ---------------- GEMM3: t[r] = b3 + sum_j relu(h2[r][j]) * w3[j]
        // Each thread: relu * w3, sum its 4 cols -> 16 row partials, then
        // butterfly-reduce over the warp (32 distinct c0 values).
        #pragma unroll
        for (int p = 0; p < 8; ++p) {
            float sa = 0.f, sb = 0.f;
            #pragma unroll
            for (int c = 0; c < 4; ++c) {
                float a, b; unpack2(acc[c][p], a, b);
                sa = fmaf(fmaxf(a, 0.f), w3v[c], sa);
                sb = fmaf(fmaxf(b, 0.f), w3v[c], sb);
            }
            #pragma unroll
            for (int o = 16; o > 0; o >>= 1) {
                sa += __shfl_xor_sync(0xffffffffu, sa, o);
                sb += __shfl_xor_sync(0xffffffffu, sb, o);
            }
            if (lane == 0) {
                // warps 2g and 2g+1 cover c0-halves of row group g
                part[(r0 + 2 * p)     * 2 + (warp & 1)] = sa;
                part[(r0 + 2 * p + 1) * 2 + (warp & 1)] = sb;
            }
        }
        __syncthreads();

        if (tid < RTILE) {
            float t = b3[step] + part[tid * 2] + part[tid * 2 + 1];
            const int tgt = (i < 63) ? i : 63;   // column receiving the update
            zs[tgt * ZS + tid] += t;
        }
        __syncthreads();
    }

    // Epilogue: out = exp(s) * z
    for (int e = tid; e < RTILE * NCOLS; e += 256) {
        int col = e & (NCOLS - 1);
        int row = e >> 6;
        out[(row0 + row) * NCOLS + col] = expf(s[col]) * zs[col * ZS + row];
    }
}

extern "C" void kernel_launch(void* const* d_in, const int* in_sizes, int n_in,
                              void* d_out, int out_size)
{
    const float* x   = (const float*)d_in[0];
    const float* s   = (const float*)d_in[1];
    const float* W1  = (const float*)d_in[2];
    const float* b1  = (const float*)d_in[3];
    const float* W2  = (const float*)d_in[4];
    const float* b2  = (const float*)d_in[5];
    const float* W3  = (const float*)d_in[6];
    const float* b3  = (const float*)d_in[7];
    const int*   idx = (const int*)d_in[8];
    float* out = (float*)d_out;

    const int B      = in_sizes[0] / NCOLS;   // 131072
    const int nsteps = in_sizes[8];           // 65

    const int smem_bytes = (NCOLS * ZS + HID * HS + RTILE * 2) * (int)sizeof(float);

    cudaFuncSetAttribute(additive_flow_kernel,
                         cudaFuncAttributeMaxDynamicSharedMemorySize, smem_bytes);

    dim3 grid(B / RTILE);   // 2048 CTAs
    dim3 block(256);
    additive_flow_kernel<<<grid, block, smem_bytes>>>(
        x, s, W1, b1, W2, b2, W3, b3, idx, out, nsteps);
}

// round 7
// speedup vs baseline: 2.8335x; 1.9540x over previous
#include <cuda_runtime.h>
#include <cuda_bf16.h>
#include <stdint.h>

// ============================================================================
// Additive flow: 65 sequential steps of a 63->256->256->1 MLP per batch row.
// tcgen05 is unavailable (harness compiles for plain sm_103, not sm_103a), so
// GEMMs run on warp-level mma.sync.m16n8k16 bf16 (HMMA), with hi/lo bf16
// split x3 products accumulated in fp32 registers for fp32-class accuracy.
// Weights are pre-packed into per-lane MMA fragment order by prologue kernels
// (one-time-ish, in-graph) so B operands are single coalesced LDG.64s shared
// by all CTAs (L2 broadcast). z tile persists in SMEM across all steps.
// ============================================================================

#define NSTEPS_MAX 65

// Fragment arrays: [step][split(hi/lo)][ktile][ntile(32)][lane(32)] x 8B
__device__ __align__(16) unsigned char g_w1f[NSTEPS_MAX * 2 * 4  * 32 * 32 * 8];
__device__ __align__(16) unsigned char g_w2f[(size_t)NSTEPS_MAX * 2 * 16 * 32 * 32 * 8];
// [step][ntile(32)][lane(32)] x float4 {b2[n0], b2[n0+1], w3[n0], w3[n0+1]}
__device__ __align__(16) unsigned char g_bw3[NSTEPS_MAX * 32 * 32 * 16];

#define W1_STEP_BYTES  (2 * 4 * 32 * 32 * 8)    // 65536
#define W1_SPLIT_BYTES (4 * 32 * 32 * 8)        // 32768
#define W2_STEP_BYTES  (2 * 16 * 32 * 32 * 8)   // 262144
#define W2_SPLIT_BYTES (16 * 32 * 32 * 8)       // 131072

// ---- SMEM layout (bytes) ----
#define ZS_OFF    0        // z: [64 cols][128 rows] fp32 = 32768
#define VH_OFF    32768    // v hi: [128 rows][64 k] bf16 = 16384 (swizzled)
#define VL_OFF    49152    // v lo
#define H1H_OFF   65536    // h1 hi: [128 rows][256 k] bf16 = 65536 (swizzled)
#define H1L_OFF   131072   // h1 lo
#define PART_OFF  196608   // [128 rows][4 colblocks] fp32 = 2048
#define SMEM_TOTAL 198656

// ---------------------------------------------------------------- helpers
static __device__ __forceinline__ uint32_t smem_u32(const void* p) {
    uint32_t a;
    asm("{ .reg .u64 t; cvta.to.shared.u64 t, %1; cvt.u32.u64 %0, t; }"
        : "=r"(a) : "l"(p));
    return a;
}

static __device__ __forceinline__ void ldm_x4(uint32_t (&r)[4], uint32_t addr) {
    asm volatile("ldmatrix.sync.aligned.m8n8.x4.shared.b16 {%0,%1,%2,%3}, [%4];"
        : "=r"(r[0]), "=r"(r[1]), "=r"(r[2]), "=r"(r[3]) : "r"(addr));
}

static __device__ __forceinline__ void mma_bf16(float (&d)[4],
                                                const uint32_t (&a)[4],
                                                uint32_t b0, uint32_t b1) {
    asm volatile(
        "mma.sync.aligned.m16n8k16.row.col.f32.bf16.bf16.f32 "
        "{%0,%1,%2,%3}, {%4,%5,%6,%7}, {%8,%9}, {%0,%1,%2,%3};"
        : "+f"(d[0]), "+f"(d[1]), "+f"(d[2]), "+f"(d[3])
        : "r"(a[0]), "r"(a[1]), "r"(a[2]), "r"(a[3]), "r"(b0), "r"(b1));
}

static __device__ __forceinline__ uint32_t packbf(float v0, float v1) {
    __nv_bfloat16 h0 = __float2bfloat16(v0);
    __nv_bfloat16 h1 = __float2bfloat16(v1);
    return (uint32_t)__bfloat16_as_ushort(h0)
         | ((uint32_t)__bfloat16_as_ushort(h1) << 16);
}

static __device__ __forceinline__ float bf_res(float v) {
    return v - __bfloat162float(__float2bfloat16(v));
}

// ---------------------------------------------------------------- prologues
// Pack W1 (63x256 per step, + bias row k=63 so v[63]=1 carries b1) into
// mma B-fragment order, bf16 hi/lo.
__global__ void pack_w1(const float* __restrict__ W1,
                        const float* __restrict__ b1, int nsteps)
{
    int t = blockIdx.x * blockDim.x + threadIdx.x;
    // t = (((step*2 + split)*4 + kt)*32 + ntg)*32 + lane
    int lane = t & 31, ntg = (t >> 5) & 31, kt = (t >> 10) & 3;
    int split = (t >> 12) & 1, step = t >> 13;
    if (step >= nsteps) return;
    int g = lane >> 2, t2 = lane & 3;
    int n = ntg * 8 + g;
    int k0 = kt * 16 + 2 * t2;
    float w[4];
    #pragma unroll
    for (int e = 0; e < 4; ++e) {
        int k = k0 + (e >> 1) * 8 + (e & 1);
        w[e] = (k < 63) ? W1[((size_t)step * 63 + k) * 256 + n]
                        : b1[step * 256 + n];
        if (split) w[e] = bf_res(w[e]);
    }
    uint2 frag = make_uint2(packbf(w[0], w[1]), packbf(w[2], w[3]));
    size_t off = ((((size_t)step * 2 + split) * 4 + kt) * 32 + ntg) * 32 + lane;
    *(uint2*)(g_w1f + off * 8) = frag;
}

__global__ void pack_w2(const float* __restrict__ W2, int nsteps)
{
    int t = blockIdx.x * blockDim.x + threadIdx.x;
    int lane = t & 31, ntg = (t >> 5) & 31, kt = (t >> 10) & 15;
    int split = (t >> 14) & 1, step = t >> 15;
    if (step >= nsteps) return;
    int g = lane >> 2, t2 = lane & 3;
    int n = ntg * 8 + g;
    int k0 = kt * 16 + 2 * t2;
    float w[4];
    #pragma unroll
    for (int e = 0; e < 4; ++e) {
        int k = k0 + (e >> 1) * 8 + (e & 1);
        w[e] = W2[((size_t)step * 256 + k) * 256 + n];
        if (split) w[e] = bf_res(w[e]);
    }
    uint2 frag = make_uint2(packbf(w[0], w[1]), packbf(w[2], w[3]));
    size_t off = ((((size_t)step * 2 + split) * 16 + kt) * 32 + ntg) * 32 + lane;
    *(uint2*)(g_w2f + off * 8) = frag;
}

__global__ void pack_bw3(const float* __restrict__ b2,
                         const float* __restrict__ W3, int nsteps)
{
    int t = blockIdx.x * blockDim.x + threadIdx.x;
    int lane = t & 31, ntg = (t >> 5) & 31, step = t >> 10;
    if (step >= nsteps) return;
    int n0 = ntg * 8 + 2 * (lane & 3);
    float4 f = make_float4(b2[step * 256 + n0], b2[step * 256 + n0 + 1],
                           W3[step * 256 + n0], W3[step * 256 + n0 + 1]);
    *(float4*)(g_bw3 + (((size_t)step * 32 + ntg) * 32 + lane) * 16) = f;
}

// ---------------------------------------------------------------- main
__global__ void __launch_bounds__(256, 1)
flow_main_kernel(const float* __restrict__ x,
                 const float* __restrict__ s,
                 const float* __restrict__ b3g,
                 const int*   __restrict__ idx,
                 float* __restrict__ out,
                 int nsteps)
{
    extern __shared__ unsigned char smem[];
    float* zs   = (float*)(smem + ZS_OFF);     // [64 cols][128 rows]
    float* part = (float*)(smem + PART_OFF);   // [128 rows][4 cbs]
    const uint32_t sb = smem_u32(smem);

    const int tid  = threadIdx.x;
    const int lane = tid & 31;
    const int w    = tid >> 5;
    const int g    = lane >> 2;
    const int t2   = lane & 3;
    const int rb   = w >> 2;          // row block (0/1): rows [64rb, 64rb+64)
    const int cb   = w & 3;           // col block (0..3): cols [64cb, 64cb+64)
    const long long row0 = (long long)blockIdx.x * 128;

    // ldmatrix lane-address components (row/k-half this lane supplies)
    const int lrow  = (lane & 7) + ((lane >> 3) & 1) * 8;  // 0..15 within tile
    const int khalf = (lane >> 4) & 1;                      // 0/1 (k or k+8)

    // Load z tile col-major: zs[c][r] = x[row0+r][c]
    for (int e = tid; e < 128 * 64; e += 256) {
        int c = e & 63, r = e >> 6;
        zs[c * 128 + r] = x[(row0 + r) * 64 + c];
    }
    __syncthreads();

    for (int step = 0; step < nsteps; ++step) {
        const int i = idx[step];

        // ---- build v (bf16 hi/lo, swizzled): v[k]=z'[k], v[i]=z63, v[63]=1
        {
            const int row  = tid & 127;
            const int half = tid >> 7;           // 0: k 0..31, 1: k 32..63
            const float z63 = zs[63 * 128 + row];
            #pragma unroll
            for (int c = 0; c < 4; ++c) {
                const int chunk = half * 4 + c;  // 8 k-values per chunk
                uint32_t hi[4], lo[4];
                #pragma unroll
                for (int e = 0; e < 4; ++e) {
                    int k0 = chunk * 8 + 2 * e, k1 = k0 + 1;
                    float v0 = (k0 == 63) ? 1.f
                             : ((k0 == i) ? z63 : zs[k0 * 128 + row]);
                    float v1 = (k1 == 63) ? 1.f
                             : ((k1 == i) ? z63 : zs[k1 * 128 + row]);
                    hi[e] = packbf(v0, v1);
                    lo[e] = packbf(bf_res(v0), bf_res(v1));
                }
                uint32_t off = (uint32_t)row * 128 + ((chunk ^ (row & 7)) << 4);
                *(uint4*)(smem + VH_OFF + off) = make_uint4(hi[0], hi[1], hi[2], hi[3]);
                *(uint4*)(smem + VL_OFF + off) = make_uint4(lo[0], lo[1], lo[2], lo[3]);
            }
        }
        __syncthreads();

        float acc[4][8][4];
        #pragma unroll
        for (int rt = 0; rt < 4; ++rt)
            #pragma unroll
            for (int nt = 0; nt < 8; ++nt)
                #pragma unroll
                for (int e = 0; e < 4; ++e) acc[rt][nt][e] = 0.f;

        // ---- GEMM1: h1 = v @ W1 (+b1 via pad row), K=64
        {
            const unsigned char* wb = g_w1f + (size_t)step * W1_STEP_BYTES;
            #pragma unroll
            for (int kt = 0; kt < 4; ++kt) {
                uint32_t Ah[4][4], Al[4][4];
                #pragma unroll
                for (int rt = 0; rt < 4; ++rt) {
                    int row = rb * 64 + rt * 16 + lrow;
                    int chunk = kt * 2 + khalf;
                    uint32_t ad = sb + (uint32_t)row * 128
                                + ((chunk ^ (row & 7)) << 4);
                    ldm_x4(Ah[rt], ad + VH_OFF);
                    ldm_x4(Al[rt], ad + VL_OFF);
                }
                #pragma unroll
                for (int nt = 0; nt < 8; ++nt) {
                    size_t fi = (((size_t)kt * 32) + cb * 8 + nt) * 32 + lane;
                    uint2 bh = *(const uint2*)(wb + fi * 8);
                    uint2 bl = *(const uint2*)(wb + W1_SPLIT_BYTES + fi * 8);
                    #pragma unroll
                    for (int rt = 0; rt < 4; ++rt) {
                        mma_bf16(acc[rt][nt], Ah[rt], bh.x, bh.y);
                        mma_bf16(acc[rt][nt], Al[rt], bh.x, bh.y);
                        mma_bf16(acc[rt][nt], Ah[rt], bl.x, bl.y);
                    }
                }
            }
        }

        // ---- epi1: relu, bf16 split, store h1 (swizzled) for GEMM2's A
        #pragma unroll
        for (int rt = 0; rt < 4; ++rt) {
            #pragma unroll
            for (int h = 0; h < 2; ++h) {
                int row = rb * 64 + rt * 16 + g + 8 * h;
                uint32_t rbase = (uint32_t)row * 512;
                uint32_t sw = (uint32_t)(row & 7);
                #pragma unroll
                for (int nt = 0; nt < 8; ++nt) {
                    float v0 = fmaxf(acc[rt][nt][2 * h],     0.f);
                    float v1 = fmaxf(acc[rt][nt][2 * h + 1], 0.f);
                    uint32_t chunk = (uint32_t)(cb * 8 + nt);
                    uint32_t off = rbase + ((chunk ^ sw) << 4) + 4 * t2;
                    *(uint32_t*)(smem + H1H_OFF + off) = packbf(v0, v1);
                    *(uint32_t*)(smem + H1L_OFF + off) = packbf(bf_res(v0), bf_res(v1));
                }
            }
        }
        __syncthreads();

        #pragma unroll
        for (int rt = 0; rt < 4; ++rt)
            #pragma unroll
            for (int nt = 0; nt < 8; ++nt)
                #pragma unroll
                for (int e = 0; e < 4; ++e) acc[rt][nt][e] = 0.f;

        // ---- GEMM2: h2 = h1 @ W2, K=256
        {
            const unsigned char* wb = g_w2f + (size_t)step * W2_STEP_BYTES;
            #pragma unroll 1
            for (int kt = 0; kt < 16; ++kt) {
                uint32_t Ah[4][4], Al[4][4];
                #pragma unroll
                for (int rt = 0; rt < 4; ++rt) {
                    int row = rb * 64 + rt * 16 + lrow;
                    int chunk = kt * 2 + khalf;
                    uint32_t ad = sb + (uint32_t)row * 512
                                + ((chunk ^ (row & 7)) << 4);
                    ldm_x4(Ah[rt], ad + H1H_OFF);
                    ldm_x4(Al[rt], ad + H1L_OFF);
                }
                #pragma unroll
                for (int nt = 0; nt < 8; ++nt) {
                    size_t fi = (((size_t)kt * 32) + cb * 8 + nt) * 32 + lane;
                    uint2 bh = *(const uint2*)(wb + fi * 8);
                    uint2 bl = *(const uint2*)(wb + W2_SPLIT_BYTES + fi * 8);
                    #pragma unroll
                    for (int rt = 0; rt < 4; ++rt) {
                        mma_bf16(acc[rt][nt], Ah[rt], bh.x, bh.y);
                        mma_bf16(acc[rt][nt], Al[rt], bh.x, bh.y);
                        mma_bf16(acc[rt][nt], Ah[rt], bl.x, bl.y);
                    }
                }
            }
        }

        // ---- GEMM3: t[r] = b3 + sum_n relu(h2[r,n] + b2[n]) * w3[n]
        {
            float p0[4], p1[4];   // per-lane row partials: rows g and g+8, per rt
            #pragma unroll
            for (int rt = 0; rt < 4; ++rt) { p0[rt] = 0.f; p1[rt] = 0.f; }
            #pragma unroll
            for (int nt = 0; nt < 8; ++nt) {
                float4 bw = *(const float4*)(g_bw3 +
                    (((size_t)step * 32 + cb * 8 + nt) * 32 + lane) * 16);
                #pragma unroll
                for (int rt = 0; rt < 4; ++rt) {
                    p0[rt] = fmaf(fmaxf(acc[rt][nt][0] + bw.x, 0.f), bw.z, p0[rt]);
                    p0[rt] = fmaf(fmaxf(acc[rt][nt][1] + bw.y, 0.f), bw.w, p0[rt]);
                    p1[rt] = fmaf(fmaxf(acc[rt][nt][2] + bw.x, 0.f), bw.z, p1[rt]);
                    p1[rt] = fmaf(fmaxf(acc[rt][nt][3] + bw.y, 0.f), bw.w, p1[rt]);
                }
            }
            #pragma unroll
            for (int rt = 0; rt < 4; ++rt) {
                #pragma unroll
                for (int o = 1; o < 4; o <<= 1) {
                    p0[rt] += __shfl_xor_sync(0xffffffffu, p0[rt], o);
                    p1[rt] += __shfl_xor_sync(0xffffffffu, p1[rt], o);
                }
                if (t2 == 0) {
                    int rowa = rb * 64 + rt * 16 + g;
                    part[rowa * 4 + cb]       = p0[rt];
                    part[(rowa + 8) * 4 + cb] = p1[rt];
                }
            }
        }
        __syncthreads();

        if (tid < 128) {
            float t = b3g[step] + part[tid * 4] + part[tid * 4 + 1]
                    + part[tid * 4 + 2] + part[tid * 4 + 3];
            const int tgt = (i < 63) ? i : 63;
            zs[tgt * 128 + tid] += t;
        }
        __syncthreads();
    }

    // Epilogue: out = exp(s) * z
    for (int e = tid; e < 128 * 64; e += 256) {
        int c = e & 63, r = e >> 6;
        out[(row0 + r) * 64 + c] = expf(s[c]) * zs[c * 128 + r];
    }
}

// ---------------------------------------------------------------- launch
extern "C" void kernel_launch(void* const* d_in, const int* in_sizes, int n_in,
                              void* d_out, int out_size)
{
    const float* x   = (const float*)d_in[0];
    const float* s   = (const float*)d_in[1];
    const float* W1  = (const float*)d_in[2];
    const float* b1  = (const float*)d_in[3];
    const float* W2  = (const float*)d_in[4];
    const float* b2  = (const float*)d_in[5];
    const float* W3  = (const float*)d_in[6];
    const float* b3  = (const float*)d_in[7];
    const int*   idx = (const int*)d_in[8];
    float* out = (float*)d_out;

    const int B      = in_sizes[0] / 64;     // 131072
    const int nsteps = in_sizes[8];          // 65

    // Prologues: pack weights into MMA-fragment order (bf16 hi/lo)
    {
        int t1 = nsteps * 2 * 4 * 32 * 32;        // 532480
        pack_w1<<<(t1 + 255) / 256, 256>>>(W1, b1, nsteps);
        int t2 = nsteps * 2 * 16 * 32 * 32;       // 2129920
        pack_w2<<<(t2 + 255) / 256, 256>>>(W2, nsteps);
        int t3 = nsteps * 32 * 32;                // 66560
        pack_bw3<<<(t3 + 255) / 256, 256>>>(b2, W3, nsteps);
    }

    cudaFuncSetAttribute(flow_main_kernel,
                         cudaFuncAttributeMaxDynamicSharedMemorySize, SMEM_TOTAL);

    dim3 grid(B / 128);   // 1024 CTAs
    dim3 block(256);
    flow_main_kernel<<<grid, block, SMEM_TOTAL>>>(
        x, s, b3, idx, out, nsteps);
}

// round 8
// speedup vs baseline: 5.9499x; 2.0998x over previous
#include <cuda_runtime.h>
#include <cuda_fp16.h>
#include <stdint.h>

// ============================================================================
// Additive flow: 65 sequential steps of a 63->256->256->1 MLP per batch row.
// Warp-level mma.sync.m16n8k16 fp16 (HMMA), 2-product split for accuracy:
//   D = Ah*Wh + Al*Wh   (A carried exactly as fp16 hi + fp16 residual;
//                        W rounded once to fp16, error ~2^-11 -> ~1e-4 final)
// Weights pre-packed into per-lane MMA fragment order by prologue kernels so
// B operands are single coalesced LDG.64s shared across CTAs (L2 broadcast).
// z tile (128 rows) persists in SMEM across all 65 steps.
// ============================================================================

#define NSTEPS_MAX 65

// W1 fragments: [step][kt(4)][ntile(32)][lane(32)] x 8B   (fp16 hi only)
__device__ __align__(16) unsigned char g_w1f[NSTEPS_MAX * 4 * 32 * 32 * 8];
// W2 fragments: [step][kt(16)][ntile(32)][lane(32)] x 8B
__device__ __align__(16) unsigned char g_w2f[(size_t)NSTEPS_MAX * 16 * 32 * 32 * 8];
// [step][ntile(32)][lane(32)] x float4 {b2[n0], b2[n0+1], w3[n0], w3[n0+1]}
__device__ __align__(16) unsigned char g_bw3[NSTEPS_MAX * 32 * 32 * 16];

#define W1_STEP_BYTES  (4 * 32 * 32 * 8)     // 32768
#define W2_STEP_BYTES  (16 * 32 * 32 * 8)    // 131072

// ---- SMEM layout (bytes) ----
#define ZS_OFF    0        // z: [64 cols][128 rows] fp32 = 32768
#define VH_OFF    32768    // v hi: [128 rows][64 k] fp16 = 16384 (swizzled)
#define VL_OFF    49152    // v lo (residual)
#define H1H_OFF   65536    // h1 hi: [128 rows][256 k] fp16 = 65536 (swizzled)
#define H1L_OFF   131072   // h1 lo
#define PART_OFF  196608   // [128 rows][4 colblocks] fp32 = 2048
#define SMEM_TOTAL 198656

// ---------------------------------------------------------------- helpers
static __device__ __forceinline__ uint32_t smem_u32(const void* p) {
    uint32_t a;
    asm("{ .reg .u64 t; cvta.to.shared.u64 t, %1; cvt.u32.u64 %0, t; }"
        : "=r"(a) : "l"(p));
    return a;
}

static __device__ __forceinline__ void ldm_x4(uint32_t (&r)[4], uint32_t addr) {
    asm volatile("ldmatrix.sync.aligned.m8n8.x4.shared.b16 {%0,%1,%2,%3}, [%4];"
        : "=r"(r[0]), "=r"(r[1]), "=r"(r[2]), "=r"(r[3]) : "r"(addr));
}

static __device__ __forceinline__ void mma_f16(float (&d)[4],
                                               const uint32_t (&a)[4],
                                               uint32_t b0, uint32_t b1) {
    asm volatile(
        "mma.sync.aligned.m16n8k16.row.col.f32.f16.f16.f32 "
        "{%0,%1,%2,%3}, {%4,%5,%6,%7}, {%8,%9}, {%0,%1,%2,%3};"
        : "+f"(d[0]), "+f"(d[1]), "+f"(d[2]), "+f"(d[3])
        : "r"(a[0]), "r"(a[1]), "r"(a[2]), "r"(a[3]), "r"(b0), "r"(b1));
}

static __device__ __forceinline__ uint32_t packhf(float v0, float v1) {
    __half h0 = __float2half_rn(v0);
    __half h1 = __float2half_rn(v1);
    return (uint32_t)__half_as_ushort(h0)
         | ((uint32_t)__half_as_ushort(h1) << 16);
}

static __device__ __forceinline__ float hf_res(float v) {
    return v - __half2float(__float2half_rn(v));
}

// ---------------------------------------------------------------- prologues
// Pack W1 (63x256 per step, + bias row k=63 so v[63]=1 carries b1) into
// mma B-fragment order, fp16.
__global__ void pack_w1(const float* __restrict__ W1,
                        const float* __restrict__ b1, int nsteps)
{
    int t = blockIdx.x * blockDim.x + threadIdx.x;
    // t = ((step*4 + kt)*32 + ntg)*32 + lane
    int lane = t & 31, ntg = (t >> 5) & 31, kt = (t >> 10) & 3;
    int step = t >> 12;
    if (step >= nsteps) return;
    int g = lane >> 2, t2 = lane & 3;
    int n = ntg * 8 + g;
    int k0 = kt * 16 + 2 * t2;
    float w[4];
    #pragma unroll
    for (int e = 0; e < 4; ++e) {
        int k = k0 + (e >> 1) * 8 + (e & 1);
        w[e] = (k < 63) ? W1[((size_t)step * 63 + k) * 256 + n]
                        : b1[step * 256 + n];
    }
    uint2 frag = make_uint2(packhf(w[0], w[1]), packhf(w[2], w[3]));
    size_t off = (((size_t)step * 4 + kt) * 32 + ntg) * 32 + lane;
    *(uint2*)(g_w1f + off * 8) = frag;
}

__global__ void pack_w2(const float* __restrict__ W2, int nsteps)
{
    int t = blockIdx.x * blockDim.x + threadIdx.x;
    int lane = t & 31, ntg = (t >> 5) & 31, kt = (t >> 10) & 15;
    int step = t >> 14;
    if (step >= nsteps) return;
    int g = lane >> 2, t2 = lane & 3;
    int n = ntg * 8 + g;
    int k0 = kt * 16 + 2 * t2;
    float w[4];
    #pragma unroll
    for (int e = 0; e < 4; ++e) {
        int k = k0 + (e >> 1) * 8 + (e & 1);
        w[e] = W2[((size_t)step * 256 + k) * 256 + n];
    }
    uint2 frag = make_uint2(packhf(w[0], w[1]), packhf(w[2], w[3]));
    size_t off = (((size_t)step * 16 + kt) * 32 + ntg) * 32 + lane;
    *(uint2*)(g_w2f + off * 8) = frag;
}

__global__ void pack_bw3(const float* __restrict__ b2,
                         const float* __restrict__ W3, int nsteps)
{
    int t = blockIdx.x * blockDim.x + threadIdx.x;
    int lane = t & 31, ntg = (t >> 5) & 31, step = t >> 10;
    if (step >= nsteps) return;
    int n0 = ntg * 8 + 2 * (lane & 3);
    float4 f = make_float4(b2[step * 256 + n0], b2[step * 256 + n0 + 1],
                           W3[step * 256 + n0], W3[step * 256 + n0 + 1]);
    *(float4*)(g_bw3 + (((size_t)step * 32 + ntg) * 32 + lane) * 16) = f;
}

// ---------------------------------------------------------------- main
__global__ void __launch_bounds__(256, 1)
flow_main_kernel(const float* __restrict__ x,
                 const float* __restrict__ s,
                 const float* __restrict__ b3g,
                 const int*   __restrict__ idx,
                 float* __restrict__ out,
                 int nsteps)
{
    extern __shared__ unsigned char smem[];
    float* zs   = (float*)(smem + ZS_OFF);     // [64 cols][128 rows]
    float* part = (float*)(smem + PART_OFF);   // [128 rows][4 cbs]
    const uint32_t sb = smem_u32(smem);

    const int tid  = threadIdx.x;
    const int lane = tid & 31;
    const int w    = tid >> 5;
    const int g    = lane >> 2;
    const int t2   = lane & 3;
    const int rb   = w >> 2;          // row block (0/1): rows [64rb, 64rb+64)
    const int cb   = w & 3;           // col block (0..3): cols [64cb, 64cb+64)
    const long long row0 = (long long)blockIdx.x * 128;

    // ldmatrix lane-address components (row/k-half this lane supplies)
    const int lrow  = (lane & 7) + ((lane >> 3) & 1) * 8;  // 0..15 within tile
    const int khalf = (lane >> 4) & 1;                      // 0/1 (k or k+8)

    // Load z tile col-major: zs[c][r] = x[row0+r][c]
    for (int e = tid; e < 128 * 64; e += 256) {
        int c = e & 63, r = e >> 6;
        zs[c * 128 + r] = x[(row0 + r) * 64 + c];
    }
    __syncthreads();

    for (int step = 0; step < nsteps; ++step) {
        const int i = idx[step];

        // ---- build v (fp16 hi/lo, swizzled): v[k]=z'[k], v[i]=z63, v[63]=1
        {
            const int row  = tid & 127;
            const int half = tid >> 7;           // 0: k 0..31, 1: k 32..63
            const float z63 = zs[63 * 128 + row];
            #pragma unroll
            for (int c = 0; c < 4; ++c) {
                const int chunk = half * 4 + c;  // 8 k-values per chunk
                uint32_t hi[4], lo[4];
                #pragma unroll
                for (int e = 0; e < 4; ++e) {
                    int k0 = chunk * 8 + 2 * e, k1 = k0 + 1;
                    float v0 = (k0 == 63) ? 1.f
                             : ((k0 == i) ? z63 : zs[k0 * 128 + row]);
                    float v1 = (k1 == 63) ? 1.f
                             : ((k1 == i) ? z63 : zs[k1 * 128 + row]);
                    hi[e] = packhf(v0, v1);
                    lo[e] = packhf(hf_res(v0), hf_res(v1));
                }
                uint32_t off = (uint32_t)row * 128 + ((chunk ^ (row & 7)) << 4);
                *(uint4*)(smem + VH_OFF + off) = make_uint4(hi[0], hi[1], hi[2], hi[3]);
                *(uint4*)(smem + VL_OFF + off) = make_uint4(lo[0], lo[1], lo[2], lo[3]);
            }
        }
        __syncthreads();

        float acc[4][8][4];
        #pragma unroll
        for (int rt = 0; rt < 4; ++rt)
            #pragma unroll
            for (int nt = 0; nt < 8; ++nt)
                #pragma unroll
                for (int e = 0; e < 4; ++e) acc[rt][nt][e] = 0.f;

        // ---- GEMM1: h1 = v @ W1 (+b1 via pad row), K=64
        {
            const unsigned char* wb = g_w1f + (size_t)step * W1_STEP_BYTES;
            #pragma unroll
            for (int kt = 0; kt < 4; ++kt) {
                uint32_t Ah[4][4], Al[4][4];
                #pragma unroll
                for (int rt = 0; rt < 4; ++rt) {
                    int row = rb * 64 + rt * 16 + lrow;
                    int chunk = kt * 2 + khalf;
                    uint32_t ad = sb + (uint32_t)row * 128
                                + ((chunk ^ (row & 7)) << 4);
                    ldm_x4(Ah[rt], ad + VH_OFF);
                    ldm_x4(Al[rt], ad + VL_OFF);
                }
                #pragma unroll
                for (int nt = 0; nt < 8; ++nt) {
                    size_t fi = (((size_t)kt * 32) + cb * 8 + nt) * 32 + lane;
                    uint2 bh = *(const uint2*)(wb + fi * 8);
                    #pragma unroll
                    for (int rt = 0; rt < 4; ++rt) {
                        mma_f16(acc[rt][nt], Ah[rt], bh.x, bh.y);
                        mma_f16(acc[rt][nt], Al[rt], bh.x, bh.y);
                    }
                }
            }
        }

        // ---- epi1: relu, fp16 split, store h1 (swizzled) for GEMM2's A
        #pragma unroll
        for (int rt = 0; rt < 4; ++rt) {
            #pragma unroll
            for (int h = 0; h < 2; ++h) {
                int row = rb * 64 + rt * 16 + g + 8 * h;
                uint32_t rbase = (uint32_t)row * 512;
                uint32_t sw = (uint32_t)(row & 7);
                #pragma unroll
                for (int nt = 0; nt < 8; ++nt) {
                    float v0 = fmaxf(acc[rt][nt][2 * h],     0.f);
                    float v1 = fmaxf(acc[rt][nt][2 * h + 1], 0.f);
                    uint32_t chunk = (uint32_t)(cb * 8 + nt);
                    uint32_t off = rbase + ((chunk ^ sw) << 4) + 4 * t2;
                    *(uint32_t*)(smem + H1H_OFF + off) = packhf(v0, v1);
                    *(uint32_t*)(smem + H1L_OFF + off) = packhf(hf_res(v0), hf_res(v1));
                }
            }
        }
        __syncthreads();

        #pragma unroll
        for (int rt = 0; rt < 4; ++rt)
            #pragma unroll
            for (int nt = 0; nt < 8; ++nt)
                #pragma unroll
                for (int e = 0; e < 4; ++e) acc[rt][nt][e] = 0.f;

        // ---- GEMM2: h2 = h1 @ W2, K=256
        {
            const unsigned char* wb = g_w2f + (size_t)step * W2_STEP_BYTES;
            #pragma unroll 1
            for (int kt = 0; kt < 16; ++kt) {
                uint32_t Ah[4][4], Al[4][4];
                #pragma unroll
                for (int rt = 0; rt < 4; ++rt) {
                    int row = rb * 64 + rt * 16 + lrow;
                    int chunk = kt * 2 + khalf;
                    uint32_t ad = sb + (uint32_t)row * 512
                                + ((chunk ^ (row & 7)) << 4);
                    ldm_x4(Ah[rt], ad + H1H_OFF);
                    ldm_x4(Al[rt], ad + H1L_OFF);
                }
                #pragma unroll
                for (int nt = 0; nt < 8; ++nt) {
                    size_t fi = (((size_t)kt * 32) + cb * 8 + nt) * 32 + lane;
                    uint2 bh = *(const uint2*)(wb + fi * 8);
                    #pragma unroll
                    for (int rt = 0; rt < 4; ++rt) {
                        mma_f16(acc[rt][nt], Ah[rt], bh.x, bh.y);
                        mma_f16(acc[rt][nt], Al[rt], bh.x, bh.y);
                    }
                }
            }
        }

        // ---- GEMM3: t[r] = b3 + sum_n relu(h2[r,n] + b2[n]) * w3[n]
        {
            float p0[4], p1[4];   // per-lane row partials: rows g and g+8, per rt
            #pragma unroll
            for (int rt = 0; rt < 4; ++rt) { p0[rt] = 0.f; p1[rt] = 0.f; }
            #pragma unroll
            for (int nt = 0; nt < 8; ++nt) {
                float4 bw = *(const float4*)(g_bw3 +
                    (((size_t)step * 32 + cb * 8 + nt) * 32 + lane) * 16);
                #pragma unroll
                for (int rt = 0; rt < 4; ++rt) {
                    p0[rt] = fmaf(fmaxf(acc[rt][nt][0] + bw.x, 0.f), bw.z, p0[rt]);
                    p0[rt] = fmaf(fmaxf(acc[rt][nt][1] + bw.y, 0.f), bw.w, p0[rt]);
                    p1[rt] = fmaf(fmaxf(acc[rt][nt][2] + bw.x, 0.f), bw.z, p1[rt]);
                    p1[rt] = fmaf(fmaxf(acc[rt][nt][3] + bw.y, 0.f), bw.w, p1[rt]);
                }
            }
            #pragma unroll
            for (int rt = 0; rt < 4; ++rt) {
                #pragma unroll
                for (int o = 1; o < 4; o <<= 1) {
                    p0[rt] += __shfl_xor_sync(0xffffffffu, p0[rt], o);
                    p1[rt] += __shfl_xor_sync(0xffffffffu, p1[rt], o);
                }
                if (t2 == 0) {
                    int rowa = rb * 64 + rt * 16 + g;
                    part[rowa * 4 + cb]       = p0[rt];
                    part[(rowa + 8) * 4 + cb] = p1[rt];
                }
            }
        }
        __syncthreads();

        if (tid < 128) {
            float t = b3g[step] + part[tid * 4] + part[tid * 4 + 1]
                    + part[tid * 4 + 2] + part[tid * 4 + 3];
            const int tgt = (i < 63) ? i : 63;
            zs[tgt * 128 + tid] += t;
        }
        __syncthreads();
    }

    // Epilogue: out = exp(s) * z
    for (int e = tid; e < 128 * 64; e += 256) {
        int c = e & 63, r = e >> 6;
        out[(row0 + r) * 64 + c] = expf(s[c]) * zs[c * 128 + r];
    }
}

// ---------------------------------------------------------------- launch
extern "C" void kernel_launch(void* const* d_in, const int* in_sizes, int n_in,
                              void* d_out, int out_size)
{
    const float* x   = (const float*)d_in[0];
    const float* s   = (const float*)d_in[1];
    const float* W1  = (const float*)d_in[2];
    const float* b1  = (const float*)d_in[3];
    const float* W2  = (const float*)d_in[4];
    const float* b2  = (const float*)d_in[5];
    const float* W3  = (const float*)d_in[6];
    const float* b3  = (const float*)d_in[7];
    const int*   idx = (const int*)d_in[8];
    float* out = (float*)d_out;

    const int B      = in_sizes[0] / 64;     // 131072
    const int nsteps = in_sizes[8];          // 65

    // Prologues: pack weights into MMA-fragment order (fp16)
    {
        int t1 = nsteps * 4 * 32 * 32;            // 266240
        pack_w1<<<(t1 + 255) / 256, 256>>>(W1, b1, nsteps);
        int t2 = nsteps * 16 * 32 * 32;           // 1064960
        pack_w2<<<(t2 + 255) / 256, 256>>>(W2, nsteps);
        int t3 = nsteps * 32 * 32;                // 66560
        pack_bw3<<<(t3 + 255) / 256, 256>>>(b2, W3, nsteps);
    }

    cudaFuncSetAttribute(flow_main_kernel,
                         cudaFuncAttributeMaxDynamicSharedMemorySize, SMEM_TOTAL);

    dim3 grid(B / 128);   // 1024 CTAs
    dim3 block(256);
    flow_main_kernel<<<grid, block, SMEM_TOTAL>>>(
        x, s, b3, idx, out, nsteps);
}

// round 9
// speedup vs baseline: 10.1761x; 1.7103x over previous
#include <cuda_runtime.h>
#include <cuda_fp16.h>
#include <stdint.h>

// ============================================================================
// Additive flow: 65 sequential steps of a 63->256->256->1 MLP per batch row.
// Warp-level mma.sync.m16n8k16 fp16 (HMMA), single product (A and W both
// rounded once to fp16; fp32 accumulate). Measured error scaling says this
// lands ~2e-4 relative, 5x under the 1e-3 gate.
// Weights pre-packed into per-lane MMA fragment order by prologue kernels so
// B operands are single coalesced LDG.64s shared across CTAs (L2 broadcast).
// z tile (128 rows) persists in SMEM across all 65 steps. 512-thread CTAs
// (16 warps, 32x64 tiles) halve the epilogue phases vs the 256-thread layout.
// ============================================================================

#define NSTEPS_MAX 65

// W1 fragments: [step][kt(4)][ntile(32)][lane(32)] x 8B   (fp16)
__device__ __align__(16) unsigned char g_w1f[NSTEPS_MAX * 4 * 32 * 32 * 8];
// W2 fragments: [step][kt(16)][ntile(32)][lane(32)] x 8B
__device__ __align__(16) unsigned char g_w2f[(size_t)NSTEPS_MAX * 16 * 32 * 32 * 8];
// [step][ntile(32)][lane(32)] x float4 {b2[n0], b2[n0+1], w3[n0], w3[n0+1]}
__device__ __align__(16) unsigned char g_bw3[NSTEPS_MAX * 32 * 32 * 16];

#define W1_STEP_BYTES  (4 * 32 * 32 * 8)     // 32768
#define W2_STEP_BYTES  (16 * 32 * 32 * 8)    // 131072

// ---- SMEM layout (bytes) ----
#define ZS_OFF    0        // z: [64 cols][128 rows] fp32 = 32768
#define VH_OFF    32768    // v: [128 rows][64 k] fp16 = 16384 (swizzled)
#define H1_OFF    49152    // h1: [128 rows][256 k] fp16 = 65536 (swizzled)
#define PART_OFF  114688   // [128 rows][4 colblocks] fp32 = 2048
#define SMEM_TOTAL 116736

// ---------------------------------------------------------------- helpers
static __device__ __forceinline__ uint32_t smem_u32(const void* p) {
    uint32_t a;
    asm("{ .reg .u64 t; cvta.to.shared.u64 t, %1; cvt.u32.u64 %0, t; }"
        : "=r"(a) : "l"(p));
    return a;
}

static __device__ __forceinline__ void ldm_x4(uint32_t (&r)[4], uint32_t addr) {
    asm volatile("ldmatrix.sync.aligned.m8n8.x4.shared.b16 {%0,%1,%2,%3}, [%4];"
        : "=r"(r[0]), "=r"(r[1]), "=r"(r[2]), "=r"(r[3]) : "r"(addr));
}

static __device__ __forceinline__ void mma_f16(float (&d)[4],
                                               const uint32_t (&a)[4],
                                               uint32_t b0, uint32_t b1) {
    asm volatile(
        "mma.sync.aligned.m16n8k16.row.col.f32.f16.f16.f32 "
        "{%0,%1,%2,%3}, {%4,%5,%6,%7}, {%8,%9}, {%0,%1,%2,%3};"
        : "+f"(d[0]), "+f"(d[1]), "+f"(d[2]), "+f"(d[3])
        : "r"(a[0]), "r"(a[1]), "r"(a[2]), "r"(a[3]), "r"(b0), "r"(b1));
}

static __device__ __forceinline__ uint32_t packhf(float v0, float v1) {
    __half h0 = __float2half_rn(v0);
    __half h1 = __float2half_rn(v1);
    return (uint32_t)__half_as_ushort(h0)
         | ((uint32_t)__half_as_ushort(h1) << 16);
}

// ---------------------------------------------------------------- prologues
// Pack W1 (63x256 per step, + bias row k=63 so v[63]=1 carries b1) into
// mma B-fragment order, fp16.
__global__ void pack_w1(const float* __restrict__ W1,
                        const float* __restrict__ b1, int nsteps)
{
    int t = blockIdx.x * blockDim.x + threadIdx.x;
    // t = ((step*4 + kt)*32 + ntg)*32 + lane
    int lane = t & 31, ntg = (t >> 5) & 31, kt = (t >> 10) & 3;
    int step = t >> 12;
    if (step >= nsteps) return;
    int g = lane >> 2, t2 = lane & 3;
    int n = ntg * 8 + g;
    int k0 = kt * 16 + 2 * t2;
    float w[4];
    #pragma unroll
    for (int e = 0; e < 4; ++e) {
        int k = k0 + (e >> 1) * 8 + (e & 1);
        w[e] = (k < 63) ? W1[((size_t)step * 63 + k) * 256 + n]
                        : b1[step * 256 + n];
    }
    uint2 frag = make_uint2(packhf(w[0], w[1]), packhf(w[2], w[3]));
    size_t off = (((size_t)step * 4 + kt) * 32 + ntg) * 32 + lane;
    *(uint2*)(g_w1f + off * 8) = frag;
}

__global__ void pack_w2(const float* __restrict__ W2, int nsteps)
{
    int t = blockIdx.x * blockDim.x + threadIdx.x;
    int lane = t & 31, ntg = (t >> 5) & 31, kt = (t >> 10) & 15;
    int step = t >> 14;
    if (step >= nsteps) return;
    int g = lane >> 2, t2 = lane & 3;
    int n = ntg * 8 + g;
    int k0 = kt * 16 + 2 * t2;
    float w[4];
    #pragma unroll
    for (int e = 0; e < 4; ++e) {
        int k = k0 + (e >> 1) * 8 + (e & 1);
        w[e] = W2[((size_t)step * 256 + k) * 256 + n];
    }
    uint2 frag = make_uint2(packhf(w[0], w[1]), packhf(w[2], w[3]));
    size_t off = (((size_t)step * 16 + kt) * 32 + ntg) * 32 + lane;
    *(uint2*)(g_w2f + off * 8) = frag;
}

__global__ void pack_bw3(const float* __restrict__ b2,
                         const float* __restrict__ W3, int nsteps)
{
    int t = blockIdx.x * blockDim.x + threadIdx.x;
    int lane = t & 31, ntg = (t >> 5) & 31, step = t >> 10;
    if (step >= nsteps) return;
    int n0 = ntg * 8 + 2 * (lane & 3);
    float4 f = make_float4(b2[step * 256 + n0], b2[step * 256 + n0 + 1],
                           W3[step * 256 + n0], W3[step * 256 + n0 + 1]);
    *(float4*)(g_bw3 + (((size_t)step * 32 + ntg) * 32 + lane) * 16) = f;
}

// ---------------------------------------------------------------- main
__global__ void __launch_bounds__(512, 1)
flow_main_kernel(const float* __restrict__ x,
                 const float* __restrict__ s,
                 const float* __restrict__ b3g,
                 const int*   __restrict__ idx,
                 float* __restrict__ out,
                 int nsteps)
{
    extern __shared__ unsigned char smem[];
    float* zs   = (float*)(smem + ZS_OFF);     // [64 cols][128 rows]
    float* part = (float*)(smem + PART_OFF);   // [128 rows][4 cbs]
    const uint32_t sb = smem_u32(smem);

    const int tid  = threadIdx.x;
    const int lane = tid & 31;
    const int w    = tid >> 5;        // 0..15
    const int g    = lane >> 2;
    const int t2   = lane & 3;
    const int rb   = w >> 2;          // row block (0..3): rows [32rb, 32rb+32)
    const int cb   = w & 3;           // col block (0..3): cols [64cb, 64cb+64)
    const long long row0 = (long long)blockIdx.x * 128;

    // ldmatrix lane-address components (row/k-half this lane supplies)
    const int lrow  = (lane & 7) + ((lane >> 3) & 1) * 8;  // 0..15 within tile
    const int khalf = (lane >> 4) & 1;                      // 0/1 (k or k+8)

    // Load z tile col-major: zs[c][r] = x[row0+r][c]
    for (int e = tid; e < 128 * 64; e += 512) {
        int c = e & 63, r = e >> 6;
        zs[c * 128 + r] = x[(row0 + r) * 64 + c];
    }
    __syncthreads();

    for (int step = 0; step < nsteps; ++step) {
        const int i = idx[step];

        // ---- build v (fp16, swizzled): v[k]=z'[k], v[i]=z63, v[63]=1
        {
            const int row  = tid & 127;
            const int half = tid >> 7;           // 0..3: 16 k-values each
            const float z63 = zs[63 * 128 + row];
            #pragma unroll
            for (int c = 0; c < 2; ++c) {
                const int chunk = half * 2 + c;  // 8 k-values per chunk
                uint32_t hi[4];
                #pragma unroll
                for (int e = 0; e < 4; ++e) {
                    int k0 = chunk * 8 + 2 * e, k1 = k0 + 1;
                    float v0 = (k0 == 63) ? 1.f
                             : ((k0 == i) ? z63 : zs[k0 * 128 + row]);
                    float v1 = (k1 == 63) ? 1.f
                             : ((k1 == i) ? z63 : zs[k1 * 128 + row]);
                    hi[e] = packhf(v0, v1);
                }
                uint32_t off = (uint32_t)row * 128 + ((chunk ^ (row & 7)) << 4);
                *(uint4*)(smem + VH_OFF + off) = make_uint4(hi[0], hi[1], hi[2], hi[3]);
            }
        }
        __syncthreads();

        float acc[2][8][4];
        #pragma unroll
        for (int rt = 0; rt < 2; ++rt)
            #pragma unroll
            for (int nt = 0; nt < 8; ++nt)
                #pragma unroll
                for (int e = 0; e < 4; ++e) acc[rt][nt][e] = 0.f;

        // ---- GEMM1: h1 = v @ W1 (+b1 via pad row), K=64
        {
            const unsigned char* wb = g_w1f + (size_t)step * W1_STEP_BYTES;
            #pragma unroll
            for (int kt = 0; kt < 4; ++kt) {
                uint32_t Ah[2][4];
                #pragma unroll
                for (int rt = 0; rt < 2; ++rt) {
                    int row = rb * 32 + rt * 16 + lrow;
                    int chunk = kt * 2 + khalf;
                    uint32_t ad = sb + VH_OFF + (uint32_t)row * 128
                                + ((chunk ^ (row & 7)) << 4);
                    ldm_x4(Ah[rt], ad);
                }
                #pragma unroll
                for (int nt = 0; nt < 8; ++nt) {
                    size_t fi = (((size_t)kt * 32) + cb * 8 + nt) * 32 + lane;
                    uint2 bh = *(const uint2*)(wb + fi * 8);
                    #pragma unroll
                    for (int rt = 0; rt < 2; ++rt)
                        mma_f16(acc[rt][nt], Ah[rt], bh.x, bh.y);
                }
            }
        }

        // ---- epi1: relu, fp16, store h1 (swizzled) for GEMM2's A
        #pragma unroll
        for (int rt = 0; rt < 2; ++rt) {
            #pragma unroll
            for (int h = 0; h < 2; ++h) {
                int row = rb * 32 + rt * 16 + g + 8 * h;
                uint32_t rbase = (uint32_t)row * 512;
                uint32_t sw = (uint32_t)(row & 7);
                #pragma unroll
                for (int nt = 0; nt < 8; ++nt) {
                    float v0 = fmaxf(acc[rt][nt][2 * h],     0.f);
                    float v1 = fmaxf(acc[rt][nt][2 * h + 1], 0.f);
                    uint32_t chunk = (uint32_t)(cb * 8 + nt);
                    uint32_t off = rbase + ((chunk ^ sw) << 4) + 4 * t2;
                    *(uint32_t*)(smem + H1_OFF + off) = packhf(v0, v1);
                }
            }
        }
        __syncthreads();

        #pragma unroll
        for (int rt = 0; rt < 2; ++rt)
            #pragma unroll
            for (int nt = 0; nt < 8; ++nt)
                #pragma unroll
                for (int e = 0; e < 4; ++e) acc[rt][nt][e] = 0.f;

        // ---- GEMM2: h2 = h1 @ W2, K=256
        {
            const unsigned char* wb = g_w2f + (size_t)step * W2_STEP_BYTES;
            #pragma unroll 1
            for (int kt = 0; kt < 16; ++kt) {
                uint32_t Ah[2][4];
                #pragma unroll
                for (int rt = 0; rt < 2; ++rt) {
                    int row = rb * 32 + rt * 16 + lrow;
                    int chunk = kt * 2 + khalf;
                    uint32_t ad = sb + H1_OFF + (uint32_t)row * 512
                                + ((chunk ^ (row & 7)) << 4);
                    ldm_x4(Ah[rt], ad);
                }
                #pragma unroll
                for (int nt = 0; nt < 8; ++nt) {
                    size_t fi = (((size_t)kt * 32) + cb * 8 + nt) * 32 + lane;
                    uint2 bh = *(const uint2*)(wb + fi * 8);
                    #pragma unroll
                    for (int rt = 0; rt < 2; ++rt)
                        mma_f16(acc[rt][nt], Ah[rt], bh.x, bh.y);
                }
            }
        }

        // ---- GEMM3: t[r] = b3 + sum_n relu(h2[r,n] + b2[n]) * w3[n]
        {
            float p0[2], p1[2];   // per-lane row partials: rows g and g+8, per rt
            #pragma unroll
            for (int rt = 0; rt < 2; ++rt) { p0[rt] = 0.f; p1[rt] = 0.f; }
            #pragma unroll
            for (int nt = 0; nt < 8; ++nt) {
                float4 bw = *(const float4*)(g_bw3 +
                    (((size_t)step * 32 + cb * 8 + nt) * 32 + lane) * 16);
                #pragma unroll
                for (int rt = 0; rt < 2; ++rt) {
                    p0[rt] = fmaf(fmaxf(acc[rt][nt][0] + bw.x, 0.f), bw.z, p0[rt]);
                    p0[rt] = fmaf(fmaxf(acc[rt][nt][1] + bw.y, 0.f), bw.w, p0[rt]);
                    p1[rt] = fmaf(fmaxf(acc[rt][nt][2] + bw.x, 0.f), bw.z, p1[rt]);
                    p1[rt] = fmaf(fmaxf(acc[rt][nt][3] + bw.y, 0.f), bw.w, p1[rt]);
                }
            }
            #pragma unroll
            for (int rt = 0; rt < 2; ++rt) {
                #pragma unroll
                for (int o = 1; o < 4; o <<= 1) {
                    p0[rt] += __shfl_xor_sync(0xffffffffu, p0[rt], o);
                    p1[rt] += __shfl_xor_sync(0xffffffffu, p1[rt], o);
                }
                if (t2 == 0) {
                    int rowa = rb * 32 + rt * 16 + g;
                    part[rowa * 4 + cb]       = p0[rt];
                    part[(rowa + 8) * 4 + cb] = p1[rt];
                }
            }
        }
        __syncthreads();

        if (tid < 128) {
            float t = b3g[step] + part[tid * 4] + part[tid * 4 + 1]
                    + part[tid * 4 + 2] + part[tid * 4 + 3];
            const int tgt = (i < 63) ? i : 63;
            zs[tgt * 128 + tid] += t;
        }
        __syncthreads();
    }

    // Epilogue: out = exp(s) * z
    for (int e = tid; e < 128 * 64; e += 512) {
        int c = e & 63, r = e >> 6;
        out[(row0 + r) * 64 + c] = expf(s[c]) * zs[c * 128 + r];
    }
}

// ---------------------------------------------------------------- launch
extern "C" void kernel_launch(void* const* d_in, const int* in_sizes, int n_in,
                              void* d_out, int out_size)
{
    const float* x   = (const float*)d_in[0];
    const float* s   = (const float*)d_in[1];
    const float* W1  = (const float*)d_in[2];
    const float* b1  = (const float*)d_in[3];
    const float* W2  = (const float*)d_in[4];
    const float* b2  = (const float*)d_in[5];
    const float* W3  = (const float*)d_in[6];
    const float* b3  = (const float*)d_in[7];
    const int*   idx = (const int*)d_in[8];
    float* out = (float*)d_out;

    const int B      = in_sizes[0] / 64;     // 131072
    const int nsteps = in_sizes[8];          // 65

    // Prologues: pack weights into MMA-fragment order (fp16)
    {
        int t1 = nsteps * 4 * 32 * 32;            // 266240
        pack_w1<<<(t1 + 255) / 256, 256>>>(W1, b1, nsteps);
        int t2 = nsteps * 16 * 32 * 32;           // 1064960
        pack_w2<<<(t2 + 255) / 256, 256>>>(W2, nsteps);
        int t3 = nsteps * 32 * 32;                // 66560
        pack_bw3<<<(t3 + 255) / 256, 256>>>(b2, W3, nsteps);
    }

    cudaFuncSetAttribute(flow_main_kernel,
                         cudaFuncAttributeMaxDynamicSharedMemorySize, SMEM_TOTAL);

    dim3 grid(B / 128);   // 1024 CTAs
    dim3 block(512);
    flow_main_kernel<<<grid, block, SMEM_TOTAL>>>(
        x, s, b3, idx, out, nsteps);
}

// round 10
// speedup vs baseline: 10.9249x; 1.0736x over previous
#include <cuda_runtime.h>
#include <cuda_fp16.h>
#include <stdint.h>

// ============================================================================
// Additive flow: 65 sequential steps of a 63->256->256->1 MLP per batch row.
// Warp-level mma.sync.m16n8k16 fp16 (HMMA), single product (A and W rounded
// once to fp16, fp32 accumulate; measured rel_err ~1.9e-4, 5x under gate).
// Weights pre-packed into per-lane MMA fragment order by prologue kernels so
// B operands are single coalesced LDG.64s shared across CTAs (L2 broadcast).
// This round: 256-thread CTAs owning 64 rows, TWO CTAs resident per SM
// (regs<=128, smem 57KB) so one CTA's MMA phases overlap the other's
// epilogue/sync phases -- the tensor pipe was idle 47% of the time with a
// single 512-thread CTA per SM.
// ============================================================================

#define NSTEPS_MAX 65

// W1 fragments: [step][kt(4)][ntile(32)][lane(32)] x 8B   (fp16)
__device__ __align__(16) unsigned char g_w1f[NSTEPS_MAX * 4 * 32 * 32 * 8];
// W2 fragments: [step][kt(16)][ntile(32)][lane(32)] x 8B
__device__ __align__(16) unsigned char g_w2f[(size_t)NSTEPS_MAX * 16 * 32 * 32 * 8];
// [step][ntile(32)][lane(32)] x float4 {b2[n0], b2[n0+1], w3[n0], w3[n0+1]}
__device__ __align__(16) unsigned char g_bw3[NSTEPS_MAX * 32 * 32 * 16];

#define W1_STEP_BYTES  (4 * 32 * 32 * 8)     // 32768
#define W2_STEP_BYTES  (16 * 32 * 32 * 8)    // 131072

// ---- SMEM layout (bytes), 64-row tile ----
#define ZS_OFF    0        // z: [64 cols][64 rows] fp32 = 16384
#define VH_OFF    16384    // v: [64 rows][64 k] fp16 = 8192 (swizzled)
#define H1_OFF    24576    // h1: [64 rows][256 k] fp16 = 32768 (swizzled)
#define PART_OFF  57344    // [64 rows][4 colblocks] fp32 = 1024
#define SMEM_TOTAL 58368

// ---------------------------------------------------------------- helpers
static __device__ __forceinline__ uint32_t smem_u32(const void* p) {
    uint32_t a;
    asm("{ .reg .u64 t; cvta.to.shared.u64 t, %1; cvt.u32.u64 %0, t; }"
        : "=r"(a) : "l"(p));
    return a;
}

static __device__ __forceinline__ void ldm_x4(uint32_t (&r)[4], uint32_t addr) {
    asm volatile("ldmatrix.sync.aligned.m8n8.x4.shared.b16 {%0,%1,%2,%3}, [%4];"
        : "=r"(r[0]), "=r"(r[1]), "=r"(r[2]), "=r"(r[3]) : "r"(addr));
}

static __device__ __forceinline__ void mma_f16(float (&d)[4],
                                               const uint32_t (&a)[4],
                                               uint32_t b0, uint32_t b1) {
    asm volatile(
        "mma.sync.aligned.m16n8k16.row.col.f32.f16.f16.f32 "
        "{%0,%1,%2,%3}, {%4,%5,%6,%7}, {%8,%9}, {%0,%1,%2,%3};"
        : "+f"(d[0]), "+f"(d[1]), "+f"(d[2]), "+f"(d[3])
        : "r"(a[0]), "r"(a[1]), "r"(a[2]), "r"(a[3]), "r"(b0), "r"(b1));
}

static __device__ __forceinline__ uint32_t packhf(float v0, float v1) {
    __half h0 = __float2half_rn(v0);
    __half h1 = __float2half_rn(v1);
    return (uint32_t)__half_as_ushort(h0)
         | ((uint32_t)__half_as_ushort(h1) << 16);
}

// ---------------------------------------------------------------- prologues
// Pack W1 (63x256 per step, + bias row k=63 so v[63]=1 carries b1) into
// mma B-fragment order, fp16.
__global__ void pack_w1(const float* __restrict__ W1,
                        const float* __restrict__ b1, int nsteps)
{
    int t = blockIdx.x * blockDim.x + threadIdx.x;
    // t = ((step*4 + kt)*32 + ntg)*32 + lane
    int lane = t & 31, ntg = (t >> 5) & 31, kt = (t >> 10) & 3;
    int step = t >> 12;
    if (step >= nsteps) return;
    int g = lane >> 2, t2 = lane & 3;
    int n = ntg * 8 + g;
    int k0 = kt * 16 + 2 * t2;
    float w[4];
    #pragma unroll
    for (int e = 0; e < 4; ++e) {
        int k = k0 + (e >> 1) * 8 + (e & 1);
        w[e] = (k < 63) ? W1[((size_t)step * 63 + k) * 256 + n]
                        : b1[step * 256 + n];
    }
    uint2 frag = make_uint2(packhf(w[0], w[1]), packhf(w[2], w[3]));
    size_t off = (((size_t)step * 4 + kt) * 32 + ntg) * 32 + lane;
    *(uint2*)(g_w1f + off * 8) = frag;
}

__global__ void pack_w2(const float* __restrict__ W2, int nsteps)
{
    int t = blockIdx.x * blockDim.x + threadIdx.x;
    int lane = t & 31, ntg = (t >> 5) & 31, kt = (t >> 10) & 15;
    int step = t >> 14;
    if (step >= nsteps) return;
    int g = lane >> 2, t2 = lane & 3;
    int n = ntg * 8 + g;
    int k0 = kt * 16 + 2 * t2;
    float w[4];
    #pragma unroll
    for (int e = 0; e < 4; ++e) {
        int k = k0 + (e >> 1) * 8 + (e & 1);
        w[e] = W2[((size_t)step * 256 + k) * 256 + n];
    }
    uint2 frag = make_uint2(packhf(w[0], w[1]), packhf(w[2], w[3]));
    size_t off = (((size_t)step * 16 + kt) * 32 + ntg) * 32 + lane;
    *(uint2*)(g_w2f + off * 8) = frag;
}

__global__ void pack_bw3(const float* __restrict__ b2,
                         const float* __restrict__ W3, int nsteps)
{
    int t = blockIdx.x * blockDim.x + threadIdx.x;
    int lane = t & 31, ntg = (t >> 5) & 31, step = t >> 10;
    if (step >= nsteps) return;
    int n0 = ntg * 8 + 2 * (lane & 3);
    float4 f = make_float4(b2[step * 256 + n0], b2[step * 256 + n0 + 1],
                           W3[step * 256 + n0], W3[step * 256 + n0 + 1]);
    *(float4*)(g_bw3 + (((size_t)step * 32 + ntg) * 32 + lane) * 16) = f;
}

// ---------------------------------------------------------------- main
__global__ void __launch_bounds__(256, 2)
flow_main_kernel(const float* __restrict__ x,
                 const float* __restrict__ s,
                 const float* __restrict__ b3g,
                 const int*   __restrict__ idx,
                 float* __restrict__ out,
                 int nsteps)
{
    extern __shared__ unsigned char smem[];
    float* zs   = (float*)(smem + ZS_OFF);     // [64 cols][64 rows]
    float* part = (float*)(smem + PART_OFF);   // [64 rows][4 cbs]
    const uint32_t sb = smem_u32(smem);

    const int tid  = threadIdx.x;
    const int lane = tid & 31;
    const int w    = tid >> 5;        // 0..7
    const int g    = lane >> 2;
    const int t2   = lane & 3;
    const int rb   = w >> 2;          // row block (0..1): rows [32rb, 32rb+32)
    const int cb   = w & 3;           // col block (0..3): cols [64cb, 64cb+64)
    const long long row0 = (long long)blockIdx.x * 64;

    // ldmatrix lane-address components (row/k-half this lane supplies)
    const int lrow  = (lane & 7) + ((lane >> 3) & 1) * 8;  // 0..15 within tile
    const int khalf = (lane >> 4) & 1;                      // 0/1 (k or k+8)

    // Load z tile col-major: zs[c][r] = x[row0+r][c]
    for (int e = tid; e < 64 * 64; e += 256) {
        int c = e & 63, r = e >> 6;
        zs[c * 64 + r] = x[(row0 + r) * 64 + c];
    }
    __syncthreads();

    for (int step = 0; step < nsteps; ++step) {
        const int i = idx[step];

        // ---- build v (fp16, swizzled): v[k]=z'[k], v[i]=z63, v[63]=1
        {
            const int row  = tid & 63;
            const int quad = tid >> 6;           // 0..3: 16 k-values each
            const float z63 = zs[63 * 64 + row];
            #pragma unroll
            for (int c = 0; c < 2; ++c) {
                const int chunk = quad * 2 + c;  // 8 k-values per chunk
                uint32_t hi[4];
                #pragma unroll
                for (int e = 0; e < 4; ++e) {
                    int k0 = chunk * 8 + 2 * e, k1 = k0 + 1;
                    float v0 = (k0 == 63) ? 1.f
                             : ((k0 == i) ? z63 : zs[k0 * 64 + row]);
                    float v1 = (k1 == 63) ? 1.f
                             : ((k1 == i) ? z63 : zs[k1 * 64 + row]);
                    hi[e] = packhf(v0, v1);
                }
                uint32_t off = (uint32_t)row * 128 + ((chunk ^ (row & 7)) << 4);
                *(uint4*)(smem + VH_OFF + off) = make_uint4(hi[0], hi[1], hi[2], hi[3]);
            }
        }
        __syncthreads();

        float acc[2][8][4];
        #pragma unroll
        for (int rt = 0; rt < 2; ++rt)
            #pragma unroll
            for (int nt = 0; nt < 8; ++nt)
                #pragma unroll
                for (int e = 0; e < 4; ++e) acc[rt][nt][e] = 0.f;

        // ---- GEMM1: h1 = v @ W1 (+b1 via pad row), K=64
        {
            const unsigned char* wb = g_w1f + (size_t)step * W1_STEP_BYTES;
            #pragma unroll
            for (int kt = 0; kt < 4; ++kt) {
                uint32_t Ah[2][4];
                #pragma unroll
                for (int rt = 0; rt < 2; ++rt) {
                    int row = rb * 32 + rt * 16 + lrow;
                    int chunk = kt * 2 + khalf;
                    uint32_t ad = sb + VH_OFF + (uint32_t)row * 128
                                + ((chunk ^ (row & 7)) << 4);
                    ldm_x4(Ah[rt], ad);
                }
                #pragma unroll
                for (int nt = 0; nt < 8; ++nt) {
                    size_t fi = (((size_t)kt * 32) + cb * 8 + nt) * 32 + lane;
                    uint2 bh = *(const uint2*)(wb + fi * 8);
                    #pragma unroll
                    for (int rt = 0; rt < 2; ++rt)
                        mma_f16(acc[rt][nt], Ah[rt], bh.x, bh.y);
                }
            }
        }

        // ---- epi1: relu, fp16, store h1 (swizzled) for GEMM2's A
        #pragma unroll
        for (int rt = 0; rt < 2; ++rt) {
            #pragma unroll
            for (int h = 0; h < 2; ++h) {
                int row = rb * 32 + rt * 16 + g + 8 * h;
                uint32_t rbase = (uint32_t)row * 512;
                uint32_t sw = (uint32_t)(row & 7);
                #pragma unroll
                for (int nt = 0; nt < 8; ++nt) {
                    float v0 = fmaxf(acc[rt][nt][2 * h],     0.f);
                    float v1 = fmaxf(acc[rt][nt][2 * h + 1], 0.f);
                    uint32_t chunk = (uint32_t)(cb * 8 + nt);
                    uint32_t off = rbase + ((chunk ^ sw) << 4) + 4 * t2;
                    *(uint32_t*)(smem + H1_OFF + off) = packhf(v0, v1);
                }
            }
        }
        __syncthreads();

        #pragma unroll
        for (int rt = 0; rt < 2; ++rt)
            #pragma unroll
            for (int nt = 0; nt < 8; ++nt)
                #pragma unroll
                for (int e = 0; e < 4; ++e) acc[rt][nt][e] = 0.f;

        // ---- GEMM2: h2 = h1 @ W2, K=256
        {
            const unsigned char* wb = g_w2f + (size_t)step * W2_STEP_BYTES;
            #pragma unroll 1
            for (int kt = 0; kt < 16; ++kt) {
                uint32_t Ah[2][4];
                #pragma unroll
                for (int rt = 0; rt < 2; ++rt) {
                    int row = rb * 32 + rt * 16 + lrow;
                    int chunk = kt * 2 + khalf;
                    uint32_t ad = sb + H1_OFF + (uint32_t)row * 512
                                + ((chunk ^ (row & 7)) << 4);
                    ldm_x4(Ah[rt], ad);
                }
                #pragma unroll
                for (int nt = 0; nt < 8; ++nt) {
                    size_t fi = (((size_t)kt * 32) + cb * 8 + nt) * 32 + lane;
                    uint2 bh = *(const uint2*)(wb + fi * 8);
                    #pragma unroll
                    for (int rt = 0; rt < 2; ++rt)
                        mma_f16(acc[rt][nt], Ah[rt], bh.x, bh.y);
                }
            }
        }

        // ---- GEMM3: t[r] = b3 + sum_n relu(h2[r,n] + b2[n]) * w3[n]
        {
            float p0[2], p1[2];   // per-lane row partials: rows g and g+8, per rt
            #pragma unroll
            for (int rt = 0; rt < 2; ++rt) { p0[rt] = 0.f; p1[rt] = 0.f; }
            #pragma unroll
            for (int nt = 0; nt < 8; ++nt) {
                float4 bw = *(const float4*)(g_bw3 +
                    (((size_t)step * 32 + cb * 8 + nt) * 32 + lane) * 16);
                #pragma unroll
                for (int rt = 0; rt < 2; ++rt) {
                    p0[rt] = fmaf(fmaxf(acc[rt][nt][0] + bw.x, 0.f), bw.z, p0[rt]);
                    p0[rt] = fmaf(fmaxf(acc[rt][nt][1] + bw.y, 0.f), bw.w, p0[rt]);
                    p1[rt] = fmaf(fmaxf(acc[rt][nt][2] + bw.x, 0.f), bw.z, p1[rt]);
                    p1[rt] = fmaf(fmaxf(acc[rt][nt][3] + bw.y, 0.f), bw.w, p1[rt]);
                }
            }
            #pragma unroll
            for (int rt = 0; rt < 2; ++rt) {
                #pragma unroll
                for (int o = 1; o < 4; o <<= 1) {
                    p0[rt] += __shfl_xor_sync(0xffffffffu, p0[rt], o);
                    p1[rt] += __shfl_xor_sync(0xffffffffu, p1[rt], o);
                }
                if (t2 == 0) {
                    int rowa = rb * 32 + rt * 16 + g;
                    part[rowa * 4 + cb]       = p0[rt];
                    part[(rowa + 8) * 4 + cb] = p1[rt];
                }
            }
        }
        __syncthreads();

        if (tid < 64) {
            float t = b3g[step] + part[tid * 4] + part[tid * 4 + 1]
                    + part[tid * 4 + 2] + part[tid * 4 + 3];
            const int tgt = (i < 63) ? i : 63;
            zs[tgt * 64 + tid] += t;
        }
        __syncthreads();
    }

    // Epilogue: out = exp(s) * z
    for (int e = tid; e < 64 * 64; e += 256) {
        int c = e & 63, r = e >> 6;
        out[(row0 + r) * 64 + c] = expf(s[c]) * zs[c * 64 + r];
    }
}

// ---------------------------------------------------------------- launch
extern "C" void kernel_launch(void* const* d_in, const int* in_sizes, int n_in,
                              void* d_out, int out_size)
{
    const float* x   = (const float*)d_in[0];
    const float* s   = (const float*)d_in[1];
    const float* W1  = (const float*)d_in[2];
    const float* b1  = (const float*)d_in[3];
    const float* W2  = (const float*)d_in[4];
    const float* b2  = (const float*)d_in[5];
    const float* W3  = (const float*)d_in[6];
    const float* b3  = (const float*)d_in[7];
    const int*   idx = (const int*)d_in[8];
    float* out = (float*)d_out;

    const int B      = in_sizes[0] / 64;     // 131072
    const int nsteps = in_sizes[8];          // 65

    // Prologues: pack weights into MMA-fragment order (fp16)
    {
        int t1 = nsteps * 4 * 32 * 32;            // 266240
        pack_w1<<<(t1 + 255) / 256, 256>>>(W1, b1, nsteps);
        int t2 = nsteps * 16 * 32 * 32;           // 1064960
        pack_w2<<<(t2 + 255) / 256, 256>>>(W2, nsteps);
        int t3 = nsteps * 32 * 32;                // 66560
        pack_bw3<<<(t3 + 255) / 256, 256>>>(b2, W3, nsteps);
    }

    cudaFuncSetAttribute(flow_main_kernel,
                         cudaFuncAttributeMaxDynamicSharedMemorySize, SMEM_TOTAL);

    dim3 grid(B / 64);    // 2048 CTAs, 2 resident per SM
    dim3 block(256);
    flow_main_kernel<<<grid, block, SMEM_TOTAL>>>(
        x, s, b3, idx, out, nsteps);
}